// round 2
// baseline (speedup 1.0000x reference)
#include <cuda_runtime.h>
#include <cuda_bf16.h>
#include <stdint.h>

#define MAX_N 100000
#define MAX_E 1600000
#define IN_DIM 128
#define HID 64
#define LAT 32

typedef unsigned long long ull;

// ---------------- device scratch (zero-at-entry invariant for deg/cnt/cursor) ---
__device__ float g_deg[MAX_N];          // 0 at entry; reset in scan1
__device__ float g_dinv[MAX_N];
__device__ int   g_cnt[MAX_N];          // 0 at entry; reset in scan3
__device__ int   g_rowptr[MAX_N + 1];
__device__ int   g_cursor[MAX_N];       // 0 at entry; reset in prop1
__device__ ull   g_cv[MAX_E];           // packed (col | val<<32)
__device__ float g_xw[(size_t)MAX_N * HID];
__device__ float g_h[(size_t)MAX_N * HID];
__device__ float g_h2[(size_t)MAX_N * HID];
__device__ int   g_bsum[256];
__device__ int   g_boff[256];

// ---------------- packed f32x2 helpers ----------------
__device__ __forceinline__ void fma2(ull& c, ull a, ull b) {
    asm("fma.rn.f32x2 %0, %1, %2, %3;" : "=l"(c) : "l"(a), "l"(b), "l"(c));
}
__device__ __forceinline__ ull dup2(float a) {
    ull r; unsigned u = __float_as_uint(a);
    asm("mov.b64 %0, {%1, %1};" : "=l"(r) : "r"(u));
    return r;
}
__device__ __forceinline__ float2 unpack2(ull v) {
    unsigned lo, hi;
    asm("mov.b64 {%0, %1}, %2;" : "=r"(lo), "=r"(hi) : "l"(v));
    return make_float2(__uint_as_float(lo), __uint_as_float(hi));
}

// int64-vs-int32 edge_index: JAX without x64 downgrades int64->int32. If int64,
// odd 32-bit words of the first entries are all zero (ids < 2^31).
__device__ __forceinline__ int detect_is64(const void* ei) {
    const int* p = (const int*)ei;
    int is64 = 1;
#pragma unroll
    for (int i = 0; i < 16; i++) is64 &= (p[2 * i + 1] == 0);
    return is64;
}
__device__ __forceinline__ int get_idx(const void* ei, int is64, long long pos) {
    return is64 ? (int)((const long long*)ei)[pos] : ((const int*)ei)[pos];
}

// ---------------- K1: fused GEMM1 (xw = x @ W1) + edge count ----------------
// blocks [0, GB): gemm, 128-row tiles, 256 thr, thread tile 4 rows x 8 cols.
// blocks [GB, GB+CB): count pass (atomics into g_deg/g_cnt).
__global__ void k_mega1(const float* __restrict__ A, const float* __restrict__ W,
                        float* __restrict__ C, int M,
                        const void* __restrict__ ei, const float* __restrict__ ew,
                        int E, int GB) {
    __shared__ __align__(16) float Bs[IN_DIM * HID];   // 32KB
    __shared__ __align__(16) float Ast[32 * 128];      // 16KB  (total = 48KB)

    if (blockIdx.x >= GB) {
        // ---- count branch ----
        int* flag = (int*)Ast;
        if (threadIdx.x == 0) flag[0] = detect_is64(ei);
        __syncthreads();
        int is64 = flag[0];
        int e = (blockIdx.x - GB) * blockDim.x + threadIdx.x;
        if (e < E) {
            int d = get_idx(ei, is64, (long long)E + e);
            atomicAdd(&g_deg[d], ew[e]);
            atomicAdd(&g_cnt[d], 1);
        }
        return;
    }

    // ---- gemm branch ----
    int tid = threadIdx.x;
    int tx = tid & 7;         // 0..7  -> cols 8*tx..8*tx+7
    int ty = tid >> 3;        // 0..31 -> rows 4*ty..4*ty+3
    int row0 = blockIdx.x * 128;

    const float4* W4 = (const float4*)W;
    float4* Bs4 = (float4*)Bs;
    for (int t = tid; t < IN_DIM * HID / 4; t += 256) Bs4[t] = W4[t];

    ull acc[4][4] = {};
    const float4* A4 = (const float4*)A;

    for (int kh = 0; kh < 4; kh++) {
        __syncthreads();
        for (int t = tid; t < 1024; t += 256) {
            int r = t >> 3, k4 = t & 7;
            int gr = row0 + r;
            float4 a = (gr < M) ? A4[(size_t)gr * 32 + kh * 8 + k4]
                                : make_float4(0.f, 0.f, 0.f, 0.f);
            Ast[(4 * k4 + 0) * 128 + r] = a.x;
            Ast[(4 * k4 + 1) * 128 + r] = a.y;
            Ast[(4 * k4 + 2) * 128 + r] = a.z;
            Ast[(4 * k4 + 3) * 128 + r] = a.w;
        }
        __syncthreads();
#pragma unroll
        for (int k = 0; k < 32; k++) {
            float4 av = *(const float4*)(Ast + k * 128 + 4 * ty);
            const float* brow = Bs + (kh * 32 + k) * 64 + 8 * tx;
            ulonglong2 b01 = *(const ulonglong2*)brow;
            ulonglong2 b23 = *(const ulonglong2*)(brow + 4);
            ull a0 = dup2(av.x), a1 = dup2(av.y), a2 = dup2(av.z), a3 = dup2(av.w);
            fma2(acc[0][0], a0, b01.x); fma2(acc[0][1], a0, b01.y);
            fma2(acc[0][2], a0, b23.x); fma2(acc[0][3], a0, b23.y);
            fma2(acc[1][0], a1, b01.x); fma2(acc[1][1], a1, b01.y);
            fma2(acc[1][2], a1, b23.x); fma2(acc[1][3], a1, b23.y);
            fma2(acc[2][0], a2, b01.x); fma2(acc[2][1], a2, b01.y);
            fma2(acc[2][2], a2, b23.x); fma2(acc[2][3], a2, b23.y);
            fma2(acc[3][0], a3, b01.x); fma2(acc[3][1], a3, b01.y);
            fma2(acc[3][2], a3, b23.x); fma2(acc[3][3], a3, b23.y);
        }
    }
#pragma unroll
    for (int i = 0; i < 4; i++) {
        int gr = row0 + 4 * ty + i;
        if (gr < M) {
            float2* cp = (float2*)C + (size_t)gr * 32 + 4 * tx;
#pragma unroll
            for (int j = 0; j < 4; j++) cp[j] = unpack2(acc[i][j]);
        }
    }
}

// ---------------- scan chain ----------------
__global__ void k_scan1(int n) {
    __shared__ int sh[1024];
    int i = blockIdx.x * 1024 + threadIdx.x;
    int v = (i < n) ? g_cnt[i] : 0;
    sh[threadIdx.x] = v;
    // fused: dinv + deg reset (deg complete after count)
    if (i < n) { g_dinv[i] = rsqrtf(1.0f + g_deg[i]); g_deg[i] = 0.0f; }
    __syncthreads();
    for (int off = 1; off < 1024; off <<= 1) {
        int t = (threadIdx.x >= off) ? sh[threadIdx.x - off] : 0;
        __syncthreads();
        sh[threadIdx.x] += t;
        __syncthreads();
    }
    if (i < n) g_rowptr[i] = sh[threadIdx.x];   // inclusive for now
    if (threadIdx.x == 1023) g_bsum[blockIdx.x] = sh[1023];
}

__global__ void k_scan2(int nb, int n) {
    if (threadIdx.x == 0) {
        int acc = 0;
        for (int b = 0; b < nb; b++) { int t = g_bsum[b]; g_boff[b] = acc; acc += t; }
        g_rowptr[n] = acc;   // == E
    }
}

__global__ void k_scan3(int n) {
    int i = blockIdx.x * blockDim.x + threadIdx.x;
    if (i < n) {
        g_rowptr[i] = g_rowptr[i] - g_cnt[i] + g_boff[i >> 10];
        g_cnt[i] = 0;  // restore invariant
    }
}

__global__ void k_fill(const void* __restrict__ ei, const float* __restrict__ ew, int E) {
    __shared__ int flag;
    if (threadIdx.x == 0) flag = detect_is64(ei);
    __syncthreads();
    int is64 = flag;
    int e = blockIdx.x * blockDim.x + threadIdx.x;
    if (e < E) {
        int s = get_idx(ei, is64, e);
        int d = get_idx(ei, is64, (long long)E + e);
        int pos = g_rowptr[d] + atomicAdd(&g_cursor[d], 1);
        float v = g_dinv[s] * ew[e] * g_dinv[d];
        g_cv[pos] = (ull)(unsigned)s | ((ull)__float_as_uint(v) << 32);
    }
}

// ---------------- propagation: warp per dst node, lane owns dim pair --------
__global__ void k_prop(const float* __restrict__ in, float* __restrict__ out,
                       const float* __restrict__ bias, int relu, int n,
                       int resetCursor) {
    int w = (blockIdx.x * blockDim.x + threadIdx.x) >> 5;
    int lane = threadIdx.x & 31;
    if (w >= n) return;
    if (resetCursor && lane == 0) g_cursor[w] = 0;  // restore invariant

    float di = g_dinv[w];
    ull acc = 0;
    ull self = ((const ull*)(in + (size_t)w * HID))[lane];
    fma2(acc, dup2(di * di), self);

    int s = g_rowptr[w];
    int e = g_rowptr[w + 1];
    int j = s;
    for (; j + 1 < e; j += 2) {
        ull cv0 = g_cv[j], cv1 = g_cv[j + 1];
        int c0 = (int)(unsigned)cv0;
        int c1 = (int)(unsigned)cv1;
        ull p0 = ((const ull*)(in + (size_t)c0 * HID))[lane];
        ull p1 = ((const ull*)(in + (size_t)c1 * HID))[lane];
        fma2(acc, dup2(__uint_as_float((unsigned)(cv0 >> 32))), p0);
        fma2(acc, dup2(__uint_as_float((unsigned)(cv1 >> 32))), p1);
    }
    if (j < e) {
        ull cv = g_cv[j];
        int c = (int)(unsigned)cv;
        ull p = ((const ull*)(in + (size_t)c * HID))[lane];
        fma2(acc, dup2(__uint_as_float((unsigned)(cv >> 32))), p);
    }

    float2 r = unpack2(acc);
    if (bias) { float2 bb = ((const float2*)bias)[lane]; r.x += bb.x; r.y += bb.y; }
    if (relu) { r.x = fmaxf(r.x, 0.0f); r.y = fmaxf(r.y, 0.0f); }
    ((float2*)out)[(size_t)w * 32 + lane] = r;
}

// ---------------- GEMM2: [mu|lv] = h2[M,64] @ [Wmu|Wlv] + bias ----------------
__global__ void k_gemm2(const float* __restrict__ A,
                        const float* __restrict__ Wmu, const float* __restrict__ Wlv,
                        const float* __restrict__ bmu, const float* __restrict__ blv,
                        float* __restrict__ Omu, float* __restrict__ Olv, int M) {
    __shared__ __align__(16) float Bs[HID * 64];   // 16KB
    __shared__ __align__(16) float Ast[32 * 128];  // 16KB
    int tid = threadIdx.x;
    int tx = tid & 7, ty = tid >> 3;
    int row0 = blockIdx.x * 128;

    // assemble B = [Wmu | Wlv] (64 rows x 64 cols)
    {
        const float4* Wm4 = (const float4*)Wmu;
        const float4* Wl4 = (const float4*)Wlv;
        float4* Bs4 = (float4*)Bs;
        for (int t = tid; t < HID * 64 / 4; t += 256) {
            int k = t >> 4;       // row
            int c4 = t & 15;      // float4 col index 0..15
            Bs4[t] = (c4 < 8) ? Wm4[k * 8 + c4] : Wl4[k * 8 + (c4 - 8)];
        }
    }

    ull acc[4][4] = {};
    const float4* A4 = (const float4*)A;
    for (int kh = 0; kh < 2; kh++) {
        __syncthreads();
        for (int t = tid; t < 1024; t += 256) {
            int r = t >> 3, k4 = t & 7;
            int gr = row0 + r;
            float4 a = (gr < M) ? A4[(size_t)gr * 16 + kh * 8 + k4]
                                : make_float4(0.f, 0.f, 0.f, 0.f);
            Ast[(4 * k4 + 0) * 128 + r] = a.x;
            Ast[(4 * k4 + 1) * 128 + r] = a.y;
            Ast[(4 * k4 + 2) * 128 + r] = a.z;
            Ast[(4 * k4 + 3) * 128 + r] = a.w;
        }
        __syncthreads();
#pragma unroll
        for (int k = 0; k < 32; k++) {
            float4 av = *(const float4*)(Ast + k * 128 + 4 * ty);
            const float* brow = Bs + (kh * 32 + k) * 64 + 8 * tx;
            ulonglong2 b01 = *(const ulonglong2*)brow;
            ulonglong2 b23 = *(const ulonglong2*)(brow + 4);
            ull a0 = dup2(av.x), a1 = dup2(av.y), a2 = dup2(av.z), a3 = dup2(av.w);
            fma2(acc[0][0], a0, b01.x); fma2(acc[0][1], a0, b01.y);
            fma2(acc[0][2], a0, b23.x); fma2(acc[0][3], a0, b23.y);
            fma2(acc[1][0], a1, b01.x); fma2(acc[1][1], a1, b01.y);
            fma2(acc[1][2], a1, b23.x); fma2(acc[1][3], a1, b23.y);
            fma2(acc[2][0], a2, b01.x); fma2(acc[2][1], a2, b01.y);
            fma2(acc[2][2], a2, b23.x); fma2(acc[2][3], a2, b23.y);
            fma2(acc[3][0], a3, b01.x); fma2(acc[3][1], a3, b01.y);
            fma2(acc[3][2], a3, b23.x); fma2(acc[3][3], a3, b23.y);
        }
    }

    // epilogue: 8|32 so tx<4 -> mu cols, tx>=4 -> lv cols
    int isMu = (tx < 4);
    const float2* bsrc = (const float2*)(isMu ? bmu : blv);
    float2* osrc = (float2*)(isMu ? Omu : Olv);
    int cpBase = isMu ? (4 * tx) : (4 * tx - 16);   // pair index within 16
#pragma unroll
    for (int i = 0; i < 4; i++) {
        int gr = row0 + 4 * ty + i;
        if (gr < M) {
#pragma unroll
            for (int j = 0; j < 4; j++) {
                float2 r = unpack2(acc[i][j]);
                float2 bb = bsrc[cpBase + j];
                r.x += bb.x; r.y += bb.y;
                osrc[(size_t)gr * 16 + cpBase + j] = r;
            }
        }
    }
}

// ---------------- launch ----------------
extern "C" void kernel_launch(void* const* d_in, const int* in_sizes, int n_in,
                              void* d_out, int out_size) {
    const float* x   = (const float*)d_in[0];
    const void*  ei  = d_in[1];
    const float* ew  = (const float*)d_in[2];
    const float* W1  = (const float*)d_in[3];
    const float* b1  = (const float*)d_in[4];
    const float* Wmu = (const float*)d_in[5];
    const float* bmu = (const float*)d_in[6];
    const float* Wlv = (const float*)d_in[7];
    const float* blv = (const float*)d_in[8];

    int N = in_sizes[0] / IN_DIM;
    int E = in_sizes[2];
    float* outp = (float*)d_out;
    float* Omu = outp;
    float* Olv = outp + (size_t)N * LAT;

    float *d_xw, *d_h, *d_h2;
    cudaGetSymbolAddress((void**)&d_xw, g_xw);
    cudaGetSymbolAddress((void**)&d_h, g_h);
    cudaGetSymbolAddress((void**)&d_h2, g_h2);

    int GB = (N + 127) / 128;           // gemm blocks
    int CB = (E + 255) / 256;           // count blocks
    int nbN = (N + 255) / 256;
    int nbE = (E + 255) / 256;
    int nbScan = (N + 1023) / 1024;
    int nbP = (N + 7) / 8;              // 8 warps/block

    k_mega1<<<GB + CB, 256>>>(x, W1, d_xw, N, ei, ew, E, GB);
    k_scan1<<<nbScan, 1024>>>(N);
    k_scan2<<<1, 32>>>(nbScan, N);
    k_scan3<<<nbN, 256>>>(N);
    k_fill<<<nbE, 256>>>(ei, ew, E);
    k_prop<<<nbP, 256>>>(d_xw, d_h, b1, 1, N, 1);
    k_prop<<<nbP, 256>>>(d_h, d_h2, nullptr, 0, N, 0);
    k_gemm2<<<GB, 256>>>(d_h2, Wmu, Wlv, bmu, blv, Omu, Olv, N);
}